// round 11
// baseline (speedup 1.0000x reference)
#include <cuda_runtime.h>
#include <cuda_fp16.h>

#define BB 128
#define TT 256
#define KDIM 50
#define KK 2500          // K*K
#define START_TAG 48
#define END_TAG 49
#define NTH 128
#define SLACK 4.0f       // steady-state exp2 args center at -SLACK (fp16-safe)

__device__ float g_vec[2][BB][64];   // [dir][seq][tag]: absolute log2 alpha/beta at split
__device__ float g_gold[2][BB];      // gold partial per (dir, seq)
__device__ float g_apart[BB];        // combined per-seq log all-paths (nats)
__device__ float g_gpart[BB];        // combined per-seq gold
__device__ int   g_pair[BB];         // per-pair arrival counters (self-resetting)
__device__ int   g_count = 0;        // global arrival counter (self-resetting)

__device__ __forceinline__ void cp16(void* dst_smem, const void* src) {
    unsigned s = (unsigned)__cvta_generic_to_shared(dst_smem);
    asm volatile("cp.async.cg.shared.global [%0], [%1], 16;\n" :: "r"(s), "l"(src));
}
__device__ __forceinline__ void cp_commit() {
    asm volatile("cp.async.commit_group;\n");
}
template <int N>
__device__ __forceinline__ void cp_wait() {
    asm volatile("cp.async.wait_group %0;\n" :: "n"(N));
}
__device__ __forceinline__ float ex2f(float x) {
    float y; asm("ex2.approx.f32 %0, %1;" : "=f"(y) : "f"(x)); return y;
}
__device__ __forceinline__ float lg2f(float x) {
    float y; asm("lg2.approx.f32 %0, %1;" : "=f"(y) : "f"(x)); return y;
}
__device__ __forceinline__ __half2 pack_h2(float x1, float x2) {
    unsigned p;
    asm("cvt.rn.f16x2.f32 %0, %1, %2;" : "=r"(p) : "f"(x2), "f"(x1));
    return *reinterpret_cast<__half2*>(&p);
}
__device__ __forceinline__ __half2 ex2_h2(__half2 ph) {
    unsigned p = *reinterpret_cast<unsigned*>(&ph);
    unsigned e;
    asm("ex2.approx.f16x2 %0, %1;" : "=r"(e) : "r"(p));
    return *reinterpret_cast<__half2*>(&e);
}

__global__ __launch_bounds__(NTH, 2)
void viterbi_half_kernel(const float* __restrict__ scores,
                         const int* __restrict__ targets,
                         const int* __restrict__ lengths,
                         float* __restrict__ out) {
    __shared__ __align__(16) float raw[4][KK];   // quad-buffered raw tiles (40 KB)
    __shared__ __align__(8) float vbuf[64];      // shifted log2 state vector
    __shared__ float r0s[2];                     // stale anchor, double buffered
    __shared__ float mxi[2];                     // init warp maxes
    __shared__ int   tg[TT];
    __shared__ int   sPair, sFin;
    __shared__ float sa[4], sg[4];

    const int bx   = blockIdx.x;
    const int dirB = bx >> 7;            // 0 = forward, 1 = backward
    const int b    = bx & (BB - 1);
    const int tid  = threadIdx.x;
    const int lane = tid & 31;
    const int wid  = tid >> 5;
    const int c    = tid >> 1;           // output tag column (active < 50)
    const int h    = tid & 1;            // half: 0 -> j in [0,26), 1 -> j in [26,50)
    const bool act = (c < KDIM);
    const int cc   = act ? c : 0;        // clamped column for SAFE addressing (ghost threads)
    const int len  = lengths[b];
    const int m    = (len + 1) >> 1;
    const int nv   = dirB ? (len - m + 1) : m;   // visits incl. bwd virtual visit 0
    const float* base = scores + (size_t)b * TT * KK;
    const float L = 1.4426950408889634f; // log2(e)
    const __half2 clamp12 = __float2half2_rn(12.0f);

    tg[tid] = targets[b * TT + tid];
    tg[tid + NTH] = targets[b * TT + tid + NTH];

    auto issue = [&](int vv) {
        bool real = (vv < nv) && (!dirB || vv >= 1);
        if (real) {
            int t = dirB ? (len - vv) : vv;
            const float4* src = (const float4*)(base + (size_t)t * KK);
            float4* dst = (float4*)raw[vv & 3];
            #pragma unroll
            for (int i = 0; i < 5; ++i) {
                int c4 = tid + i * NTH;
                if (c4 < 625) cp16(dst + c4, src + c4);
            }
        }
        cp_commit();                     // always commit: static group accounting
    };

    issue(0); issue(1); issue(2); issue(3);
    cp_wait<3>();
    __syncthreads();                     // visit 0 certified

    float gold = 0.f, r = 0.f, shift = 0.f, dcur = 0.f;

    // ---- init state at the starting end ----
    if (!dirB) {
        r = act ? raw[0][START_TAG * KDIM + c] * L : -1e30f;
        float mw = r;                    // all lanes execute (collective outside divergence)
        #pragma unroll
        for (int o = 16; o > 0; o >>= 1)
            mw = fmaxf(mw, __shfl_xor_sync(0xFFFFFFFFu, mw, o));
        if (lane == 0) mxi[wid & 1] = mw;   // warps 0,1 cover all 50 cols; 2,3 duplicate
        if (tid == 0) gold += raw[0][tg[0]];
    } else {
        r = (c == END_TAG) ? 0.f : -1e30f;
    }
    __syncthreads();                     // mxi visible
    if (!dirB) {
        dcur = fmaxf(mxi[0], mxi[1]) + SLACK;   // exact-max anchor at init
        if (h == 0) vbuf[c] = act ? (r - dcur) : 0.f;  // only c<64 slots exist; c<50 used
        if (tid == 0) r0s[0] = r;
    } else {
        dcur = 0.f;
        if (h == 0) vbuf[c] = r;
        if (tid == 0) r0s[0] = 0.f;
    }

    const int j0 = h ? 26 : 0;           // this thread's j-range start
    const int np = h ? 12 : 13;          // pairs in this half

    for (int v = 1; v < nv; ++v) {
        cp_wait<2>();                    // tile v landed
        __syncthreads();                 // SINGLE barrier: tile v + vbuf certified
        issue(v + 3);                    // into slot (v-1)&3 (fully drained)

        const float* sb = raw[v & 3];
        const int t = dirB ? (len - v) : v;
        if (tid == 0) gold += sb[tg[t]];

        // --- whole body executed by ALL threads (ghosts use cc, results discarded) ---
        const float2* ab2 = (const float2*)(vbuf + j0);
        __half2 acc0 = __float2half2_rn(0.f);
        __half2 acc1 = __float2half2_rn(0.f);
        if (!dirB) {                     // fwd: addr j*50 + c (column access)
            const float* col = sb + j0 * KDIM + cc;
            #pragma unroll 13
            for (int p = 0; p < np; ++p) {
                float2 av = ab2[p];
                float x1 = __fmaf_rn(col[(2 * p) * KDIM],     L, av.x);
                float x2 = __fmaf_rn(col[(2 * p + 1) * KDIM], L, av.y);
                __half2 e = ex2_h2(__hmin2(pack_h2(x1, x2), clamp12));
                if (p & 1) acc1 = __hadd2(acc1, e);
                else       acc0 = __hadd2(acc0, e);
            }
        } else {                         // bwd: addr c*50 + k (contiguous row chunk)
            const float2* row = (const float2*)(sb + cc * KDIM + j0);
            #pragma unroll 13
            for (int p = 0; p < np; ++p) {
                float2 sv = row[p];
                float2 av = ab2[p];
                float x1 = __fmaf_rn(sv.x, L, av.x);
                float x2 = __fmaf_rn(sv.y, L, av.y);
                __half2 e = ex2_h2(__hmin2(pack_h2(x1, x2), clamp12));
                if (p & 1) acc1 = __hadd2(acc1, e);
                else       acc0 = __hadd2(acc0, e);
            }
        }
        float2 f0 = __half22float2(acc0);
        float2 f1 = __half22float2(acc1);
        float tot = (f0.x + f1.x) + (f0.y + f1.y);
        tot += __shfl_xor_sync(0xFFFFFFFFu, tot, 1);   // combine halves (all lanes present)
        r = lg2f(fmaxf(tot, 1e-35f));                  // never -inf
        shift += dcur;
        float dn = r0s[(v - 1) & 1] + SLACK;           // stale anchor r_{v-1}[0]
        if (act && h == 0) vbuf[c] = r - dn;           // predicated STORES only
        dcur = dn;
        if (tid == 0) r0s[v & 1] = r;
    }

    cp_wait<0>();
    __syncthreads();

    // ---- publish half-result ----
    if (act && h == 0) g_vec[dirB][b][c] = r + shift;   // absolute log2
    if (tid == 0) g_gold[dirB][b] = gold;
    __syncthreads();
    if (tid == 0) {
        __threadfence();
        sPair = atomicAdd(&g_pair[b], 1);
    }
    __syncthreads();

    if (sPair == 1) {                    // second arrival: combine the pair
        __threadfence();
        if (tid < 32) {
            int j2 = tid + 32;
            float x1 = g_vec[0][b][tid] + g_vec[1][b][tid];
            float x2 = (j2 < KDIM) ? (g_vec[0][b][j2] + g_vec[1][b][j2]) : -1e30f;
            float mx = fmaxf(x1, x2);
            #pragma unroll
            for (int o = 16; o > 0; o >>= 1)
                mx = fmaxf(mx, __shfl_xor_sync(0xFFFFFFFFu, mx, o));
            float s = ex2f(x1 - mx) + ex2f(x2 - mx);
            #pragma unroll
            for (int o = 16; o > 0; o >>= 1)
                s += __shfl_xor_sync(0xFFFFFFFFu, s, o);
            if (tid == 0) {
                g_apart[b] = (mx + lg2f(s)) * 0.6931471805599453f;
                g_gpart[b] = g_gold[0][b] + g_gold[1][b];
                g_pair[b]  = 0;          // reset for next graph replay
            }
        }
    }
    __syncthreads();
    if (tid == 0) {
        __threadfence();
        int old = atomicAdd(&g_count, 1);
        sFin = (old == 2 * BB - 1) ? 1 : 0;
    }
    __syncthreads();

    if (sFin) {                          // very last CTA: deterministic final reduce
        __threadfence();
        float a  = g_apart[tid];         // NTH == BB == 128
        float gd = g_gpart[tid];
        #pragma unroll
        for (int o = 16; o > 0; o >>= 1) {
            a  += __shfl_down_sync(0xFFFFFFFFu, a, o);
            gd += __shfl_down_sync(0xFFFFFFFFu, gd, o);
        }
        if (lane == 0) { sa[wid] = a; sg[wid] = gd; }
        __syncthreads();
        if (tid == 0) {
            float A = sa[0] + sa[1] + sa[2] + sa[3];
            float G = sg[0] + sg[1] + sg[2] + sg[3];
            out[0] = (A - G) / (float)BB;
            atomicExch(&g_count, 0);     // reset for next graph replay
        }
    }
}

extern "C" void kernel_launch(void* const* d_in, const int* in_sizes, int n_in,
                              void* d_out, int out_size) {
    const float* scores  = (const float*)d_in[0];
    const int*   targets = (const int*)d_in[1];
    const int*   lengths = (const int*)d_in[2];
    // d_in[3] = tmap_correct (unused scalar)
    viterbi_half_kernel<<<2 * BB, NTH>>>(scores, targets, lengths, (float*)d_out);
}

// round 12
// speedup vs baseline: 1.2959x; 1.2959x over previous
#include <cuda_runtime.h>
#include <cuda_fp16.h>

#define BB 128
#define TT 256
#define KDIM 50
#define KK 2500          // K*K
#define START_TAG 48
#define END_TAG 49
#define NTH 128
#define SLACK 4.0f       // steady-state exp2 args center at -SLACK (fp16-safe)

__device__ float g_vec[2][BB][64];   // [dir][seq][tag]: absolute log2 alpha/beta at split
__device__ float g_gold[2][BB];      // gold partial per (dir, seq)
__device__ float g_apart[BB];        // combined per-seq log all-paths (nats)
__device__ float g_gpart[BB];        // combined per-seq gold
__device__ int   g_pair[BB];         // per-pair arrival counters (self-resetting)
__device__ int   g_count = 0;        // global arrival counter (self-resetting)

__device__ __forceinline__ void cp16(void* dst_smem, const void* src) {
    unsigned s = (unsigned)__cvta_generic_to_shared(dst_smem);
    asm volatile("cp.async.cg.shared.global [%0], [%1], 16;\n" :: "r"(s), "l"(src));
}
__device__ __forceinline__ void cp_commit() {
    asm volatile("cp.async.commit_group;\n");
}
template <int N>
__device__ __forceinline__ void cp_wait() {
    asm volatile("cp.async.wait_group %0;\n" :: "n"(N));
}
__device__ __forceinline__ float ex2f(float x) {
    float y; asm("ex2.approx.f32 %0, %1;" : "=f"(y) : "f"(x)); return y;
}
__device__ __forceinline__ float lg2f(float x) {
    float y; asm("lg2.approx.f32 %0, %1;" : "=f"(y) : "f"(x)); return y;
}
__device__ __forceinline__ __half2 pack_h2(float x1, float x2) {
    unsigned p;
    asm("cvt.rn.f16x2.f32 %0, %1, %2;" : "=r"(p) : "f"(x2), "f"(x1));
    return *reinterpret_cast<__half2*>(&p);
}
__device__ __forceinline__ __half2 ex2_h2(__half2 ph) {
    unsigned p = *reinterpret_cast<unsigned*>(&ph);
    unsigned e;
    asm("ex2.approx.f16x2 %0, %1;" : "=r"(e) : "r"(p));
    return *reinterpret_cast<__half2*>(&e);
}

__global__ __launch_bounds__(NTH, 2)
void viterbi_half_kernel(const float* __restrict__ scores,
                         const int* __restrict__ targets,
                         const int* __restrict__ lengths,
                         float* __restrict__ out) {
    // raw: 4 tile slots + 128-float pad (ghost-pair overflow of slot 3 lands here)
    __shared__ __align__(16) float raw[4 * KK + 128];
    __shared__ __align__(8) float vbuf[2][64];   // double-buffered state (no same-phase race)
    __shared__ float r0s[2];                     // stale anchor, double buffered
    __shared__ float mxi[2];                     // init warp maxes
    __shared__ int   tg[TT];
    __shared__ int   sPair, sFin;
    __shared__ float sa[4], sg[4];

    const int bx   = blockIdx.x;
    const int dirB = bx >> 7;            // 0 = forward, 1 = backward
    const int b    = bx & (BB - 1);
    const int tid  = threadIdx.x;
    const int lane = tid & 31;
    const int wid  = tid >> 5;
    const int c    = tid >> 1;           // output tag column (active < 50)
    const int h    = tid & 1;            // half: 0 -> j in [0,26), 1 -> j in [26,50)+ghost
    const bool act = (c < KDIM);
    const int cc   = act ? c : 0;        // clamped column for safe ghost addressing
    const int len  = lengths[b];
    const int m    = (len + 1) >> 1;
    const int nv   = dirB ? (len - m + 1) : m;   // visits incl. bwd virtual visit 0
    const float* base = scores + (size_t)b * TT * KK;
    const float L = 1.4426950408889634f; // log2(e)
    const __half2 clamp12 = __float2half2_rn(12.0f);
    const int j0 = h ? 26 : 0;           // this thread's j-range start (13 pairs each)

    tg[tid] = targets[b * TT + tid];
    tg[tid + NTH] = targets[b * TT + tid + NTH];
    if (tid < 128) raw[4 * KK + tid] = 0.f;      // zero the overflow pad once

    auto issue = [&](int vv) {
        bool real = (vv < nv) && (!dirB || vv >= 1);
        if (real) {
            int t = dirB ? (len - vv) : vv;
            const float4* src = (const float4*)(base + (size_t)t * KK);
            float4* dst = (float4*)(raw + (vv & 3) * KK);
            #pragma unroll
            for (int i = 0; i < 5; ++i) {
                int c4 = tid + i * NTH;
                if (c4 < 625) cp16(dst + c4, src + c4);
            }
        }
        cp_commit();                     // always commit: static group accounting
    };

    issue(0); issue(1); issue(2); issue(3);
    cp_wait<3>();
    __syncthreads();                     // visit 0 certified, pad zeroed

    float gold = 0.f, r = 0.f, shift = 0.f, dcur = 0.f;

    // ---- init state at the starting end ----
    if (!dirB) {
        r = act ? raw[START_TAG * KDIM + c] * L : -1e30f;
        float mw = r;                    // collective executed by ALL lanes
        #pragma unroll
        for (int o = 16; o > 0; o >>= 1)
            mw = fmaxf(mw, __shfl_xor_sync(0xFFFFFFFFu, mw, o));
        if (lane == 0) mxi[wid & 1] = mw;   // warps 0,1 cover all 50 cols; 2,3 duplicate
        if (tid == 0) gold += raw[tg[0]];
    } else {
        r = (c == END_TAG) ? 0.f : -1e30f;
    }
    __syncthreads();                     // mxi visible
    if (!dirB) {
        dcur = fmaxf(mxi[0], mxi[1]) + SLACK;   // exact-max anchor at init
        if (h == 0) {                    // pad slots 50..63 = -1e30 in BOTH buffers
            vbuf[1][c] = act ? (r - dcur) : -1e30f;
            vbuf[0][c] = -1e30f;
        }
        if (tid == 0) r0s[0] = r;
    } else {
        dcur = 0.f;
        if (h == 0) { vbuf[1][c] = r; vbuf[0][c] = -1e30f; }
        if (tid == 0) r0s[0] = 0.f;
    }

    for (int v = 1; v < nv; ++v) {
        cp_wait<2>();                    // tile v landed
        __syncthreads();                 // SINGLE barrier: tile v + vbuf[v&1] certified
        issue(v + 3);                    // into slot (v-1)&3 (fully drained)

        const float* sb = raw + (v & 3) * KK;
        const int t = dirB ? (len - v) : v;
        if (tid == 0) gold += sb[tg[t]];

        // --- all threads execute (ghost threads/pairs produce zeros) ---
        const float2* ab2 = (const float2*)(vbuf[v & 1] + j0);
        __half2 acc0 = __float2half2_rn(0.f);
        __half2 acc1 = __float2half2_rn(0.f);
        if (!dirB) {                     // fwd: addr j*50 + c (column access)
            const float* col = sb + j0 * KDIM + cc;
            #pragma unroll
            for (int p = 0; p < 13; ++p) {       // CONSTANT trip: fully unrolled, batched LDS
                float2 av = ab2[p];
                float x1 = __fmaf_rn(col[(2 * p) * KDIM],     L, av.x);
                float x2 = __fmaf_rn(col[(2 * p + 1) * KDIM], L, av.y);
                __half2 e = ex2_h2(__hmin2(pack_h2(x1, x2), clamp12));
                if (p & 1) acc1 = __hadd2(acc1, e);
                else       acc0 = __hadd2(acc0, e);
            }
        } else {                         // bwd: addr c*50 + k (contiguous row chunk)
            const float2* row = (const float2*)(sb + cc * KDIM + j0);
            #pragma unroll
            for (int p = 0; p < 13; ++p) {
                float2 sv = row[p];
                float2 av = ab2[p];
                float x1 = __fmaf_rn(sv.x, L, av.x);
                float x2 = __fmaf_rn(sv.y, L, av.y);
                __half2 e = ex2_h2(__hmin2(pack_h2(x1, x2), clamp12));
                if (p & 1) acc1 = __hadd2(acc1, e);
                else       acc0 = __hadd2(acc0, e);
            }
        }
        float2 f0 = __half22float2(acc0);
        float2 f1 = __half22float2(acc1);
        float tot = (f0.x + f1.x) + (f0.y + f1.y);
        tot += __shfl_xor_sync(0xFFFFFFFFu, tot, 1);   // combine halves (all lanes present)
        r = lg2f(fmaxf(tot, 1e-35f));                  // never -inf
        shift += dcur;
        float dn = r0s[(v - 1) & 1] + SLACK;           // stale anchor r_{v-1}[0]
        if (act && h == 0) vbuf[(v + 1) & 1][c] = r - dn;  // write OTHER buffer
        dcur = dn;
        if (tid == 0) r0s[v & 1] = r;
    }

    cp_wait<0>();
    __syncthreads();

    // ---- publish half-result ----
    if (act && h == 0) g_vec[dirB][b][c] = r + shift;   // absolute log2
    if (tid == 0) g_gold[dirB][b] = gold;
    __syncthreads();
    if (tid == 0) {
        __threadfence();
        sPair = atomicAdd(&g_pair[b], 1);
    }
    __syncthreads();

    if (sPair == 1) {                    // second arrival: combine the pair
        __threadfence();
        if (tid < 32) {
            int j2 = tid + 32;
            float x1 = g_vec[0][b][tid] + g_vec[1][b][tid];
            float x2 = (j2 < KDIM) ? (g_vec[0][b][j2] + g_vec[1][b][j2]) : -1e30f;
            float mx = fmaxf(x1, x2);
            #pragma unroll
            for (int o = 16; o > 0; o >>= 1)
                mx = fmaxf(mx, __shfl_xor_sync(0xFFFFFFFFu, mx, o));
            float s = ex2f(x1 - mx) + ex2f(x2 - mx);
            #pragma unroll
            for (int o = 16; o > 0; o >>= 1)
                s += __shfl_xor_sync(0xFFFFFFFFu, s, o);
            if (tid == 0) {
                g_apart[b] = (mx + lg2f(s)) * 0.6931471805599453f;
                g_gpart[b] = g_gold[0][b] + g_gold[1][b];
                g_pair[b]  = 0;          // reset for next graph replay
            }
        }
    }
    __syncthreads();
    if (tid == 0) {
        __threadfence();
        int old = atomicAdd(&g_count, 1);
        sFin = (old == 2 * BB - 1) ? 1 : 0;
    }
    __syncthreads();

    if (sFin) {                          // very last CTA: deterministic final reduce
        __threadfence();
        float a  = g_apart[tid];         // NTH == BB == 128
        float gd = g_gpart[tid];
        #pragma unroll
        for (int o = 16; o > 0; o >>= 1) {
            a  += __shfl_down_sync(0xFFFFFFFFu, a, o);
            gd += __shfl_down_sync(0xFFFFFFFFu, gd, o);
        }
        if (lane == 0) { sa[wid] = a; sg[wid] = gd; }
        __syncthreads();
        if (tid == 0) {
            float A = sa[0] + sa[1] + sa[2] + sa[3];
            float G = sg[0] + sg[1] + sg[2] + sg[3];
            out[0] = (A - G) / (float)BB;
            atomicExch(&g_count, 0);     // reset for next graph replay
        }
    }
}

extern "C" void kernel_launch(void* const* d_in, const int* in_sizes, int n_in,
                              void* d_out, int out_size) {
    const float* scores  = (const float*)d_in[0];
    const int*   targets = (const int*)d_in[1];
    const int*   lengths = (const int*)d_in[2];
    // d_in[3] = tmap_correct (unused scalar)
    viterbi_half_kernel<<<2 * BB, NTH>>>(scores, targets, lengths, (float*)d_out);
}